// round 2
// baseline (speedup 1.0000x reference)
#include <cuda_runtime.h>
#include <cuda_fp16.h>
#include <cstdint>

#define BATCH 32768
#define NF 162
#define KPAD 176           // 162 padded to multiple of 16
#define ACCN 1024
#define XW 2048            // concat width
#define NB 8

// ---------------- scratch (device globals; no allocations allowed) ----------------
__device__ __half g_F[(size_t)2 * BATCH * KPAD];     // packed fp16 features, stm rows then nstm rows
__device__ __half g_X[(size_t)BATCH * XW];           // activated accumulator outputs (fp16)
__device__ __half g_h1[BATCH * 32];                  // selected+clipped layer1 outputs
__device__ __half g_Wt[KPAD * ACCN];                 // W_acc^T (k-major), fp16, zero-padded k>=162
__device__ __half g_W1t[XW * 256];                   // W1^T [k][n], fp16
__device__ float  g_psqt_s[BATCH];
__device__ float  g_psqt_n[BATCH];
__device__ int    g_bucket[BATCH];

// ---------------- small packing kernels ----------------
__global__ void __launch_bounds__(256) pack_wt(const float* __restrict__ Wacc) {
    int idx = blockIdx.x * 256 + threadIdx.x;
    if (idx >= KPAD * ACCN) return;
    int k = idx >> 10, j = idx & 1023;
    float v = (k < NF) ? Wacc[(size_t)j * NF + k] : 0.f;
    g_Wt[idx] = __float2half_rn(v);
}

__global__ void __launch_bounds__(256) pack_w1t(const float* __restrict__ W1) {
    int idx = blockIdx.x * 256 + threadIdx.x;
    if (idx >= XW * 256) return;
    int n = idx >> 11, k = idx & 2047;            // coalesced read of W1[n][k]
    g_W1t[(size_t)k * 256 + n] = __float2half_rn(W1[idx]);
}

// One warp per (side,row): pack fp16 features (zero-padded), piece count -> bucket, psqt dot.
__global__ void __launch_bounds__(256) feat_kernel(const float* __restrict__ stm,
                                                   const float* __restrict__ nstm,
                                                   const float* __restrict__ Wacc) {
    int warp = (blockIdx.x * 256 + threadIdx.x) >> 5;
    int lane = threadIdx.x & 31;
    if (warp >= 2 * BATCH) return;
    const float* WaccLast = Wacc + (size_t)ACCN * NF;   // row 1024 of W_acc
    const float* src = (warp < BATCH) ? stm + (size_t)warp * NF
                                      : nstm + (size_t)(warp - BATCH) * NF;
    __half* dst = g_F + (size_t)warp * KPAD;
    float cnt = 0.f, ps = 0.f;
    for (int k = lane; k < KPAD; k += 32) {
        float v = (k < NF) ? src[k] : 0.f;
        dst[k] = __float2half_rn(v);
        cnt += v;
        ps  += v * ((k < NF) ? WaccLast[k] : 0.f);
    }
    #pragma unroll
    for (int o = 16; o; o >>= 1) {
        cnt += __shfl_down_sync(0xffffffffu, cnt, o);
        ps  += __shfl_down_sync(0xffffffffu, ps,  o);
    }
    if (lane == 0) {
        if (warp < BATCH) {
            int pc = (int)(cnt + 0.5f);
            int b  = pc / 20;
            g_bucket[warp] = (b > NB - 1) ? NB - 1 : b;
            g_psqt_s[warp] = ps;
        } else {
            g_psqt_n[warp - BATCH] = ps;
        }
    }
}

// ---------------- fp16 mma.sync GEMM, BM=128 BN=64 BK=16, 256 threads, double-buffered ----------------
__device__ __forceinline__ uint32_t smem_u32(const void* p) {
    return (uint32_t)__cvta_generic_to_shared(p);
}

// MODE 1: A=g_F [65536 x 176], B=g_Wt [176 x 1024], epilogue bias+clip^2 -> g_X (stm/nstm halves)
// MODE 2: A=g_X [32768 x 2048], B=g_W1t [2048 x 256], epilogue bias+clip+bucket select -> g_h1
template <int MODE>
__global__ void __launch_bounds__(256) gemm_kernel(const float* __restrict__ bias) {
    constexpr int KT  = (MODE == 1) ? (KPAD / 16) : (XW / 16);
    constexpr int LDA = (MODE == 1) ? KPAD : XW;
    constexpr int LDB = (MODE == 1) ? ACCN : 256;
    const __half* __restrict__ A = (MODE == 1) ? g_F : g_X;
    const __half* __restrict__ B = (MODE == 1) ? g_Wt : g_W1t;

    __shared__ __align__(16) __half As[2][128 * 24];   // stride 24 halves: conflict-free ldmatrix
    __shared__ __align__(16) __half Bs[2][16 * 72];    // stride 72 halves: conflict-free ldmatrix

    const int tid  = threadIdx.x;
    const int lane = tid & 31, wid = tid >> 5;
    const int wm = wid & 3, wn = wid >> 2;              // 4 x 2 warp grid -> 128 x 64 tile
    const int m0 = blockIdx.x * 128;
    const int n0 = blockIdx.y * 64;

    float acc[2][4][4];
    #pragma unroll
    for (int i = 0; i < 2; ++i)
        #pragma unroll
        for (int j = 0; j < 4; ++j)
            #pragma unroll
            for (int k = 0; k < 4; ++k) acc[i][j][k] = 0.f;

    const int arow = tid >> 1, ach = tid & 1;
    const __half* gA = A + (size_t)(m0 + arow) * LDA + ach * 8;
    const int brow = tid >> 3, bnc = tid & 7;
    const __half* gB = B + (size_t)brow * LDB + n0 + bnc * 8;

    auto issue = [&](int buf, int kt) {
        uint32_t sa = smem_u32(&As[buf][arow * 24 + ach * 8]);
        asm volatile("cp.async.cg.shared.global [%0], [%1], 16;\n" :: "r"(sa), "l"(gA + kt * 16));
        if (tid < 128) {
            uint32_t sb = smem_u32(&Bs[buf][brow * 72 + bnc * 8]);
            asm volatile("cp.async.cg.shared.global [%0], [%1], 16;\n"
                         :: "r"(sb), "l"(gB + (size_t)kt * 16 * LDB));
        }
        asm volatile("cp.async.commit_group;\n");
    };

    issue(0, 0);
    for (int kt = 0; kt < KT; ++kt) {
        const int buf = kt & 1;
        if (kt + 1 < KT) {
            issue(buf ^ 1, kt + 1);
            asm volatile("cp.async.wait_group 1;\n");
        } else {
            asm volatile("cp.async.wait_group 0;\n");
        }
        __syncthreads();

        uint32_t af[2][4], bf[4][2];
        #pragma unroll
        for (int mf = 0; mf < 2; ++mf) {
            const __half* p = &As[buf][(wm * 32 + mf * 16 + ((lane >> 3) & 1) * 8 + (lane & 7)) * 24
                                       + (lane >> 4) * 8];
            asm volatile("ldmatrix.sync.aligned.m8n8.x4.shared.b16 {%0,%1,%2,%3}, [%4];\n"
                         : "=r"(af[mf][0]), "=r"(af[mf][1]), "=r"(af[mf][2]), "=r"(af[mf][3])
                         : "r"(smem_u32(p)));
        }
        #pragma unroll
        for (int ng = 0; ng < 2; ++ng) {
            const __half* p = &Bs[buf][(((lane >> 3) & 1) * 8 + (lane & 7)) * 72
                                       + wn * 32 + ng * 16 + (lane >> 4) * 8];
            uint32_t r0, r1, r2, r3;
            asm volatile("ldmatrix.sync.aligned.m8n8.x4.trans.shared.b16 {%0,%1,%2,%3}, [%4];\n"
                         : "=r"(r0), "=r"(r1), "=r"(r2), "=r"(r3) : "r"(smem_u32(p)));
            bf[ng * 2 + 0][0] = r0; bf[ng * 2 + 0][1] = r1;
            bf[ng * 2 + 1][0] = r2; bf[ng * 2 + 1][1] = r3;
        }
        #pragma unroll
        for (int mf = 0; mf < 2; ++mf)
            #pragma unroll
            for (int nf = 0; nf < 4; ++nf)
                asm volatile(
                    "mma.sync.aligned.m16n8k16.row.col.f32.f16.f16.f32 "
                    "{%0,%1,%2,%3}, {%4,%5,%6,%7}, {%8,%9}, {%0,%1,%2,%3};\n"
                    : "+f"(acc[mf][nf][0]), "+f"(acc[mf][nf][1]),
                      "+f"(acc[mf][nf][2]), "+f"(acc[mf][nf][3])
                    : "r"(af[mf][0]), "r"(af[mf][1]), "r"(af[mf][2]), "r"(af[mf][3]),
                      "r"(bf[nf][0]), "r"(bf[nf][1]));
        __syncthreads();
    }

    // epilogue: c0=(g,2t) c1=(g,2t+1) c2=(g+8,2t) c3=(g+8,2t+1)
    const int g = lane >> 2, t4 = lane & 3;
    #pragma unroll
    for (int mf = 0; mf < 2; ++mf) {
        #pragma unroll
        for (int nf = 0; nf < 4; ++nf) {
            const int col = n0 + wn * 32 + nf * 8 + 2 * t4;
            #pragma unroll
            for (int h = 0; h < 2; ++h) {
                const int row = m0 + wm * 32 + mf * 16 + g + h * 8;
                const float c0 = acc[mf][nf][h * 2 + 0];
                const float c1 = acc[mf][nf][h * 2 + 1];
                if (MODE == 1) {
                    float v0 = __saturatef(c0 + bias[col]);     v0 *= v0;
                    float v1 = __saturatef(c1 + bias[col + 1]); v1 *= v1;
                    const size_t off = (row < BATCH)
                        ? (size_t)row * XW + col
                        : (size_t)(row - BATCH) * XW + ACCN + col;
                    *(__half2*)(g_X + off) = __floats2half2_rn(v0, v1);
                } else {
                    const int bk = g_bucket[row];
                    if ((col >> 5) == bk) {
                        const float v0 = __saturatef(c0 + bias[col]);
                        const float v1 = __saturatef(c1 + bias[col + 1]);
                        *(__half2*)(g_h1 + row * 32 + (col & 31)) = __floats2half2_rn(v0, v1);
                    }
                }
            }
        }
    }
}

// ---------------- final tiny layers (W2/W3 in smem) + PSQT ----------------
__global__ void __launch_bounds__(256) final_kernel(const float* __restrict__ W2,
                                                    const float* __restrict__ b2,
                                                    const float* __restrict__ W3,
                                                    const float* __restrict__ b3,
                                                    float* __restrict__ out) {
    __shared__ float sW2[NB * 32 * 32];
    __shared__ float sb2[NB * 32];
    __shared__ float sW3[NB * 32];
    __shared__ float sb3[NB];
    for (int i = threadIdx.x; i < NB * 32 * 32; i += 256) sW2[i] = W2[i];
    for (int i = threadIdx.x; i < NB * 32; i += 256) { sb2[i] = b2[i]; sW3[i] = W3[i]; }
    if (threadIdx.x < NB) sb3[threadIdx.x] = b3[threadIdx.x];
    __syncthreads();

    const int r = blockIdx.x * 256 + threadIdx.x;
    if (r >= BATCH) return;

    float hr[32];
    const __half2* hp = (const __half2*)(g_h1 + r * 32);
    #pragma unroll
    for (int j = 0; j < 16; ++j) {
        float2 f = __half22float2(hp[j]);
        hr[2 * j] = f.x; hr[2 * j + 1] = f.y;
    }
    const int bk = g_bucket[r];
    float o = 0.f;
    #pragma unroll 4
    for (int i = 0; i < 32; ++i) {
        float s = sb2[bk * 32 + i];
        const float* wr = &sW2[(bk * 32 + i) * 32];
        #pragma unroll
        for (int j = 0; j < 32; ++j) s += wr[j] * hr[j];
        s = __saturatef(s);
        o += sW3[bk * 32 + i] * s;
    }
    o += sb3[bk] + 0.5f * (g_psqt_s[r] - g_psqt_n[r]);
    out[r] = o;
}

// ---------------- launch ----------------
extern "C" void kernel_launch(void* const* d_in, const int* in_sizes, int n_in,
                              void* d_out, int out_size) {
    const float* stm  = (const float*)d_in[0];
    const float* nstm = (const float*)d_in[1];
    const float* Wacc = (const float*)d_in[2];
    const float* bacc = (const float*)d_in[3];
    const float* W1   = (const float*)d_in[4];
    const float* b1   = (const float*)d_in[5];
    const float* W2   = (const float*)d_in[6];
    const float* b2   = (const float*)d_in[7];
    const float* W3   = (const float*)d_in[8];
    const float* b3   = (const float*)d_in[9];
    float* out = (float*)d_out;

    pack_wt<<<(KPAD * ACCN + 255) / 256, 256>>>(Wacc);
    pack_w1t<<<(XW * 256 + 255) / 256, 256>>>(W1);
    feat_kernel<<<(2 * BATCH) / 8, 256>>>(stm, nstm, Wacc);   // 8 warps per block

    dim3 g1((2 * BATCH) / 128, ACCN / 64);
    gemm_kernel<1><<<g1, 256>>>(bacc);

    dim3 g2(BATCH / 128, 256 / 64);
    gemm_kernel<2><<<g2, 256>>>(b1);

    final_kernel<<<BATCH / 256, 256>>>(W2, b2, W3, b3, out);
}

// round 3
// speedup vs baseline: 1.2415x; 1.2415x over previous
#include <cuda_runtime.h>
#include <cuda_fp16.h>
#include <cstdint>

#define BATCH 32768
#define NF 162
#define KPAD 176           // 162 padded to multiple of 16
#define ACCN 1024
#define XW 2048            // concat width
#define NB 8
#define MAXT 264           // max 128-row tiles for bucket-compacted GEMM2

// ---------------- scratch (device globals; no allocations allowed) ----------------
__device__ __half g_F[(size_t)2 * BATCH * KPAD];     // packed fp16 features, stm rows then nstm rows
__device__ __half g_X[(size_t)BATCH * XW];           // activated accumulator outputs (fp16)
__device__ __half g_h1c[(size_t)MAXT * 128 * 32];    // compacted layer1 outputs (by pos)
__device__ __half g_Wt[KPAD * ACCN];                 // W_acc^T (k-major), fp16, zero-padded k>=162
__device__ __half g_W1t[XW * 256];                   // W1^T [k][n], fp16
__device__ float  g_psqt_s[BATCH];
__device__ float  g_psqt_n[BATCH];
__device__ int    g_bucket[BATCH];
__device__ int    g_cnt[NB];
__device__ int    g_fill[NB];
__device__ int    g_seg[NB];                         // 128-aligned segment starts
__device__ int    g_perm[MAXT * 128];                // bucket-sorted row ids, -1 = pad
__device__ int    g_tilebk[MAXT];
__device__ int    g_tilem0[MAXT];
__device__ int    g_ntiles;

__device__ __forceinline__ uint32_t smem_u32(const void* p) {
    return (uint32_t)__cvta_generic_to_shared(p);
}

// ---------------- init / packing kernels ----------------
__global__ void __launch_bounds__(256) init_kernel() {
    int idx = blockIdx.x * 256 + threadIdx.x;
    if (idx < MAXT * 128) g_perm[idx] = -1;
    if (idx < NB) { g_cnt[idx] = 0; g_fill[idx] = 0; }
}

__global__ void __launch_bounds__(256) pack_wt(const float* __restrict__ Wacc) {
    int idx = blockIdx.x * 256 + threadIdx.x;
    if (idx >= KPAD * ACCN) return;
    int k = idx >> 10, j = idx & 1023;
    float v = (k < NF) ? Wacc[(size_t)j * NF + k] : 0.f;
    g_Wt[idx] = __float2half_rn(v);
}

__global__ void __launch_bounds__(256) pack_w1t(const float* __restrict__ W1) {
    int idx = blockIdx.x * 256 + threadIdx.x;
    if (idx >= XW * 256) return;
    int n = idx >> 11, k = idx & 2047;            // coalesced read of W1[n][k]
    g_W1t[(size_t)k * 256 + n] = __float2half_rn(W1[idx]);
}

// One warp per (side,row): pack fp16 features, piece count -> bucket (+histogram), psqt dot.
__global__ void __launch_bounds__(256) feat_kernel(const float* __restrict__ stm,
                                                   const float* __restrict__ nstm,
                                                   const float* __restrict__ Wacc) {
    int warp = (blockIdx.x * 256 + threadIdx.x) >> 5;
    int lane = threadIdx.x & 31;
    if (warp >= 2 * BATCH) return;
    const float* WaccLast = Wacc + (size_t)ACCN * NF;   // row 1024 of W_acc
    const float* src = (warp < BATCH) ? stm + (size_t)warp * NF
                                      : nstm + (size_t)(warp - BATCH) * NF;
    __half* dst = g_F + (size_t)warp * KPAD;
    float cnt = 0.f, ps = 0.f;
    for (int k = lane; k < KPAD; k += 32) {
        float v = (k < NF) ? src[k] : 0.f;
        dst[k] = __float2half_rn(v);
        cnt += v;
        ps  += v * ((k < NF) ? WaccLast[k] : 0.f);
    }
    #pragma unroll
    for (int o = 16; o; o >>= 1) {
        cnt += __shfl_down_sync(0xffffffffu, cnt, o);
        ps  += __shfl_down_sync(0xffffffffu, ps,  o);
    }
    if (lane == 0) {
        if (warp < BATCH) {
            int pc = (int)(cnt + 0.5f);
            int b  = pc / 20;
            b = (b > NB - 1) ? NB - 1 : b;
            g_bucket[warp] = b;
            atomicAdd(&g_cnt[b], 1);
            g_psqt_s[warp] = ps;
        } else {
            g_psqt_n[warp - BATCH] = ps;
        }
    }
}

// single-thread: segment starts (128-aligned) + tile table
__global__ void prefix_kernel() {
    int s = 0, t = 0;
    for (int b = 0; b < NB; ++b) {
        g_seg[b] = s;
        int nt = (g_cnt[b] + 127) >> 7;
        for (int i = 0; i < nt; ++i) { g_tilebk[t + i] = b; g_tilem0[t + i] = s + i * 128; }
        t += nt;
        s += nt * 128;
    }
    g_ntiles = t;
}

__global__ void __launch_bounds__(256) scatter_kernel() {
    int r = blockIdx.x * 256 + threadIdx.x;
    if (r >= BATCH) return;
    int b = g_bucket[r];
    int pos = g_seg[b] + atomicAdd(&g_fill[b], 1);
    g_perm[pos] = r;
}

// ---------------- GEMM1: persistent, B-resident in smem ----------------
// A = g_F [65536 x 176], B = g_Wt [176 x 1024]. grid (9 m-slots, 16 n-tiles).
// Each block: load B tile (176x64) once; stream m-tiles (full 128x176 A tile, double buffered).
#define BSTR 72     // Bs row stride (halves)
#define ASTR 184    // As row stride (halves)
#define G1_SMEM ((176 * BSTR + 2 * 128 * ASTR) * 2)

__global__ void __launch_bounds__(256) gemm1_kernel(const float* __restrict__ bias) {
    extern __shared__ __half sh[];
    __half* Bs = sh;                       // [176][BSTR]
    __half* As = sh + 176 * BSTR;          // [2][128][ASTR]

    const int tid  = threadIdx.x;
    const int lane = tid & 31, wid = tid >> 5;
    const int wm = wid & 3, wn = wid >> 2;          // 4 x 2 warps -> 128 x 64
    const int n0 = blockIdx.y * 64;
    const int mslot = blockIdx.x;                   // 0..8

    // load B tile once (176 rows x 64 halves = 8 chunks of 16B per row)
    for (int idx = tid; idx < 176 * 8; idx += 256) {
        int k = idx >> 3, c = idx & 7;
        uint32_t d = smem_u32(Bs + k * BSTR + c * 8);
        asm volatile("cp.async.cg.shared.global [%0], [%1], 16;\n"
                     :: "r"(d), "l"(g_Wt + k * ACCN + n0 + c * 8));
    }

    const int arow = tid >> 1;                 // 128 rows, 2 threads/row
    const int acb  = (tid & 1) * 11;           // 11 chunks of 16B per half-row
    auto loadA = [&](int buf, int mt) {
        const __half* src = g_F + (size_t)(mt * 128 + arow) * KPAD + acb * 8;
        uint32_t dst = smem_u32(As + buf * (128 * ASTR) + arow * ASTR + acb * 8);
        #pragma unroll
        for (int c = 0; c < 11; ++c)
            asm volatile("cp.async.cg.shared.global [%0], [%1], 16;\n"
                         :: "r"(dst + c * 16), "l"(src + c * 8));
    };

    int mt0 = mslot;
    loadA(0, mt0);
    asm volatile("cp.async.commit_group;\n");

    const int g = lane >> 2, t4 = lane & 3;
    int buf = 0;
    for (int mt = mt0; mt < 512; mt += 9) {
        if (mt + 9 < 512) {
            loadA(buf ^ 1, mt + 9);
            asm volatile("cp.async.commit_group;\n");
            asm volatile("cp.async.wait_group 1;\n");
        } else {
            asm volatile("cp.async.wait_group 0;\n");
        }
        __syncthreads();

        float acc[2][4][4];
        #pragma unroll
        for (int i = 0; i < 2; ++i)
            #pragma unroll
            for (int j = 0; j < 4; ++j)
                #pragma unroll
                for (int k = 0; k < 4; ++k) acc[i][j][k] = 0.f;

        const __half* Ab = As + buf * (128 * ASTR);
        #pragma unroll
        for (int kt = 0; kt < 11; ++kt) {
            uint32_t af[2][4], bf[4][2];
            #pragma unroll
            for (int mf = 0; mf < 2; ++mf) {
                const __half* p = Ab + (wm * 32 + mf * 16 + ((lane >> 3) & 1) * 8 + (lane & 7)) * ASTR
                                     + kt * 16 + (lane >> 4) * 8;
                asm volatile("ldmatrix.sync.aligned.m8n8.x4.shared.b16 {%0,%1,%2,%3}, [%4];\n"
                             : "=r"(af[mf][0]), "=r"(af[mf][1]), "=r"(af[mf][2]), "=r"(af[mf][3])
                             : "r"(smem_u32(p)));
            }
            #pragma unroll
            for (int ng = 0; ng < 2; ++ng) {
                const __half* p = Bs + (kt * 16 + ((lane >> 3) & 1) * 8 + (lane & 7)) * BSTR
                                     + wn * 32 + ng * 16 + (lane >> 4) * 8;
                uint32_t r0, r1, r2, r3;
                asm volatile("ldmatrix.sync.aligned.m8n8.x4.trans.shared.b16 {%0,%1,%2,%3}, [%4];\n"
                             : "=r"(r0), "=r"(r1), "=r"(r2), "=r"(r3) : "r"(smem_u32(p)));
                bf[ng * 2 + 0][0] = r0; bf[ng * 2 + 0][1] = r1;
                bf[ng * 2 + 1][0] = r2; bf[ng * 2 + 1][1] = r3;
            }
            #pragma unroll
            for (int mf = 0; mf < 2; ++mf)
                #pragma unroll
                for (int nf = 0; nf < 4; ++nf)
                    asm volatile(
                        "mma.sync.aligned.m16n8k16.row.col.f32.f16.f16.f32 "
                        "{%0,%1,%2,%3}, {%4,%5,%6,%7}, {%8,%9}, {%0,%1,%2,%3};\n"
                        : "+f"(acc[mf][nf][0]), "+f"(acc[mf][nf][1]),
                          "+f"(acc[mf][nf][2]), "+f"(acc[mf][nf][3])
                        : "r"(af[mf][0]), "r"(af[mf][1]), "r"(af[mf][2]), "r"(af[mf][3]),
                          "r"(bf[nf][0]), "r"(bf[nf][1]));
        }
        __syncthreads();   // reads of As[buf] done -> safe to refill next iter

        // epilogue: bias + clip^2 -> g_X
        #pragma unroll
        for (int mf = 0; mf < 2; ++mf) {
            #pragma unroll
            for (int nf = 0; nf < 4; ++nf) {
                const int col = n0 + wn * 32 + nf * 8 + 2 * t4;
                #pragma unroll
                for (int h = 0; h < 2; ++h) {
                    const int row = mt * 128 + wm * 32 + mf * 16 + g + h * 8;
                    float v0 = __saturatef(acc[mf][nf][h * 2 + 0] + bias[col]);     v0 *= v0;
                    float v1 = __saturatef(acc[mf][nf][h * 2 + 1] + bias[col + 1]); v1 *= v1;
                    const size_t off = (row < BATCH)
                        ? (size_t)row * XW + col
                        : (size_t)(row - BATCH) * XW + ACCN + col;
                    *(__half2*)(g_X + off) = __floats2half2_rn(v0, v1);
                }
            }
        }
        buf ^= 1;
    }
}

// ---------------- GEMM2: bucket-compacted, M=ntiles*128, N=32, K=2048 ----------------
#define A2STR 40
__global__ void __launch_bounds__(256) gemm2_kernel(const float* __restrict__ b1) {
    __shared__ __align__(16) __half As[2][128 * A2STR];
    __shared__ __align__(16) __half Bs[2][32 * A2STR];
    __shared__ int sperm[128];

    if (blockIdx.x >= g_ntiles) return;
    const int bk = g_tilebk[blockIdx.x];
    const int m0 = g_tilem0[blockIdx.x];

    const int tid  = threadIdx.x;
    const int lane = tid & 31, wid = tid >> 5;
    const int wm = wid & 3, wn = wid >> 2;         // warp tile 32m x 16n

    if (tid < 128) sperm[tid] = g_perm[m0 + tid];
    __syncthreads();

    const int arow = tid >> 1;
    const int ac2  = (tid & 1) * 2;
    int rp = sperm[arow]; if (rp < 0) rp = 0;
    const __half* gA = g_X + (size_t)rp * XW + ac2 * 8;
    const int brow = tid >> 2, bc = tid & 3;
    const __half* gB = g_W1t + (size_t)brow * 256 + bk * 32 + bc * 8;

    auto issue = [&](int bufi, int kt) {
        uint32_t sa = smem_u32(&As[bufi][arow * A2STR + ac2 * 8]);
        #pragma unroll
        for (int c = 0; c < 2; ++c)
            asm volatile("cp.async.cg.shared.global [%0], [%1], 16;\n"
                         :: "r"(sa + c * 16), "l"(gA + kt * 32 + c * 8));
        if (tid < 128) {
            uint32_t sb = smem_u32(&Bs[bufi][brow * A2STR + bc * 8]);
            asm volatile("cp.async.cg.shared.global [%0], [%1], 16;\n"
                         :: "r"(sb), "l"(gB + (size_t)kt * 32 * 256));
        }
        asm volatile("cp.async.commit_group;\n");
    };

    float acc[2][2][4];
    #pragma unroll
    for (int i = 0; i < 2; ++i)
        #pragma unroll
        for (int j = 0; j < 2; ++j)
            #pragma unroll
            for (int k = 0; k < 4; ++k) acc[i][j][k] = 0.f;

    issue(0, 0);
    const int KT = XW / 32;
    for (int kt = 0; kt < KT; ++kt) {
        const int bufi = kt & 1;
        if (kt + 1 < KT) {
            issue(bufi ^ 1, kt + 1);
            asm volatile("cp.async.wait_group 1;\n");
        } else {
            asm volatile("cp.async.wait_group 0;\n");
        }
        __syncthreads();

        #pragma unroll
        for (int ks = 0; ks < 2; ++ks) {
            uint32_t af[2][4], bf[2][2];
            #pragma unroll
            for (int mf = 0; mf < 2; ++mf) {
                const __half* p = &As[bufi][(wm * 32 + mf * 16 + ((lane >> 3) & 1) * 8 + (lane & 7)) * A2STR
                                            + ks * 16 + (lane >> 4) * 8];
                asm volatile("ldmatrix.sync.aligned.m8n8.x4.shared.b16 {%0,%1,%2,%3}, [%4];\n"
                             : "=r"(af[mf][0]), "=r"(af[mf][1]), "=r"(af[mf][2]), "=r"(af[mf][3])
                             : "r"(smem_u32(p)));
            }
            {
                const __half* p = &Bs[bufi][(ks * 16 + ((lane >> 3) & 1) * 8 + (lane & 7)) * A2STR
                                            + wn * 16 + (lane >> 4) * 8];
                uint32_t r0, r1, r2, r3;
                asm volatile("ldmatrix.sync.aligned.m8n8.x4.trans.shared.b16 {%0,%1,%2,%3}, [%4];\n"
                             : "=r"(r0), "=r"(r1), "=r"(r2), "=r"(r3) : "r"(smem_u32(p)));
                bf[0][0] = r0; bf[0][1] = r1;
                bf[1][0] = r2; bf[1][1] = r3;
            }
            #pragma unroll
            for (int mf = 0; mf < 2; ++mf)
                #pragma unroll
                for (int nf = 0; nf < 2; ++nf)
                    asm volatile(
                        "mma.sync.aligned.m16n8k16.row.col.f32.f16.f16.f32 "
                        "{%0,%1,%2,%3}, {%4,%5,%6,%7}, {%8,%9}, {%0,%1,%2,%3};\n"
                        : "+f"(acc[mf][nf][0]), "+f"(acc[mf][nf][1]),
                          "+f"(acc[mf][nf][2]), "+f"(acc[mf][nf][3])
                        : "r"(af[mf][0]), "r"(af[mf][1]), "r"(af[mf][2]), "r"(af[mf][3]),
                          "r"(bf[nf][0]), "r"(bf[nf][1]));
        }
        __syncthreads();
    }

    // epilogue: bias + clip -> compacted h1
    const int g = lane >> 2, t4 = lane & 3;
    #pragma unroll
    for (int mf = 0; mf < 2; ++mf) {
        #pragma unroll
        for (int nf = 0; nf < 2; ++nf) {
            const int col = wn * 16 + nf * 8 + 2 * t4;
            #pragma unroll
            for (int h = 0; h < 2; ++h) {
                const int rl = wm * 32 + mf * 16 + g + h * 8;
                if (sperm[rl] >= 0) {
                    const float v0 = __saturatef(acc[mf][nf][h * 2 + 0] + b1[bk * 32 + col]);
                    const float v1 = __saturatef(acc[mf][nf][h * 2 + 1] + b1[bk * 32 + col + 1]);
                    *(__half2*)(g_h1c + (size_t)(m0 + rl) * 32 + col) = __floats2half2_rn(v0, v1);
                }
            }
        }
    }
}

// ---------------- final tiny layers (W2/W3 in smem) + PSQT ----------------
__global__ void __launch_bounds__(256) final_kernel(const float* __restrict__ W2,
                                                    const float* __restrict__ b2,
                                                    const float* __restrict__ W3,
                                                    const float* __restrict__ b3,
                                                    float* __restrict__ out) {
    __shared__ float sW2[NB * 32 * 32];
    __shared__ float sb2[NB * 32];
    __shared__ float sW3[NB * 32];
    __shared__ float sb3[NB];
    for (int i = threadIdx.x; i < NB * 32 * 32; i += 256) sW2[i] = W2[i];
    for (int i = threadIdx.x; i < NB * 32; i += 256) { sb2[i] = b2[i]; sW3[i] = W3[i]; }
    if (threadIdx.x < NB) sb3[threadIdx.x] = b3[threadIdx.x];
    __syncthreads();

    const int pos = blockIdx.x * 256 + threadIdx.x;
    const int r = g_perm[pos];
    if (r < 0) return;

    float hr[32];
    const __half2* hp = (const __half2*)(g_h1c + (size_t)pos * 32);
    #pragma unroll
    for (int j = 0; j < 16; ++j) {
        float2 f = __half22float2(hp[j]);
        hr[2 * j] = f.x; hr[2 * j + 1] = f.y;
    }
    const int bk = g_bucket[r];
    float o = 0.f;
    #pragma unroll 4
    for (int i = 0; i < 32; ++i) {
        float s = sb2[bk * 32 + i];
        const float* wr = &sW2[(bk * 32 + i) * 32];
        #pragma unroll
        for (int j = 0; j < 32; ++j) s += wr[j] * hr[j];
        s = __saturatef(s);
        o += sW3[bk * 32 + i] * s;
    }
    o += sb3[bk] + 0.5f * (g_psqt_s[r] - g_psqt_n[r]);
    out[r] = o;
}

// ---------------- launch ----------------
extern "C" void kernel_launch(void* const* d_in, const int* in_sizes, int n_in,
                              void* d_out, int out_size) {
    const float* stm  = (const float*)d_in[0];
    const float* nstm = (const float*)d_in[1];
    const float* Wacc = (const float*)d_in[2];
    const float* bacc = (const float*)d_in[3];
    const float* W1   = (const float*)d_in[4];
    const float* b1   = (const float*)d_in[5];
    const float* W2   = (const float*)d_in[6];
    const float* b2   = (const float*)d_in[7];
    const float* W3   = (const float*)d_in[8];
    const float* b3   = (const float*)d_in[9];
    float* out = (float*)d_out;

    cudaFuncSetAttribute(gemm1_kernel, cudaFuncAttributeMaxDynamicSharedMemorySize, G1_SMEM);

    init_kernel<<<(MAXT * 128 + 255) / 256, 256>>>();
    pack_wt<<<(KPAD * ACCN + 255) / 256, 256>>>(Wacc);
    pack_w1t<<<(XW * 256 + 255) / 256, 256>>>(W1);
    feat_kernel<<<(2 * BATCH) / 8, 256>>>(stm, nstm, Wacc);
    prefix_kernel<<<1, 1>>>();
    scatter_kernel<<<BATCH / 256, 256>>>();

    dim3 g1(9, ACCN / 64);
    gemm1_kernel<<<g1, 256, G1_SMEM>>>(bacc);

    gemm2_kernel<<<MAXT, 256>>>(b1);

    final_kernel<<<(MAXT * 128) / 256, 256>>>(W2, b2, W3, b3, out);
}

// round 4
// speedup vs baseline: 1.7595x; 1.4173x over previous
#include <cuda_runtime.h>
#include <cuda_fp16.h>
#include <cstdint>

#define BATCH 32768
#define NF 162
#define KPAD 176           // 162 padded to multiple of 16
#define ACCN 1024
#define XW 2048            // concat width
#define NB 8
#define MAXT 264           // max 128-row tiles for bucket-compacted GEMM2

// ---------------- scratch (device globals; no allocations allowed) ----------------
__device__ __half g_F[(size_t)2 * BATCH * KPAD];     // packed fp16 features, stm rows then nstm rows
__device__ __half g_X[(size_t)BATCH * XW];           // activated accumulator outputs (fp16)
__device__ __half g_Wt[KPAD * ACCN];                 // W_acc^T (k-major), fp16, zero-padded k>=162
__device__ __half g_W1t[XW * 256];                   // W1^T [k][n], fp16
__device__ float  g_psqt_s[BATCH];
__device__ float  g_psqt_n[BATCH];
__device__ int    g_bucket[BATCH];
__device__ int    g_cnt[NB];
__device__ int    g_fill[NB];
__device__ int    g_seg[NB];                         // 128-aligned segment starts
__device__ int    g_perm[MAXT * 128];                // bucket-sorted row ids, -1 = pad
__device__ int    g_tilebk[MAXT];
__device__ int    g_tilem0[MAXT];
__device__ int    g_ntiles;

__device__ __forceinline__ uint32_t smem_u32(const void* p) {
    return (uint32_t)__cvta_generic_to_shared(p);
}

// ---------------- setup: pack weights + init tables (one kernel) ----------------
__global__ void __launch_bounds__(256) setup_kernel(const float* __restrict__ Wacc,
                                                    const float* __restrict__ W1) {
    int idx = blockIdx.x * 256 + threadIdx.x;
    if (idx < KPAD * ACCN) {
        int k = idx >> 10, j = idx & 1023;
        float v = (k < NF) ? Wacc[(size_t)j * NF + k] : 0.f;
        g_Wt[idx] = __float2half_rn(v);
    }
    if (idx < XW * 256) {
        int n = idx >> 11, k = idx & 2047;           // coalesced read of W1[n][k]
        g_W1t[(size_t)k * 256 + n] = __float2half_rn(W1[idx]);
    }
    if (idx < MAXT * 128) g_perm[idx] = -1;
    if (idx < NB) { g_cnt[idx] = 0; g_fill[idx] = 0; }
}

// ---------------- feature pack: one warp per (side,row), vectorized x2 ----------------
__global__ void __launch_bounds__(256) feat_kernel(const float* __restrict__ stm,
                                                   const float* __restrict__ nstm,
                                                   const float* __restrict__ Wacc) {
    int warp = (blockIdx.x * 256 + threadIdx.x) >> 5;
    int lane = threadIdx.x & 31;
    if (warp >= 2 * BATCH) return;
    const float2* WaccLast = (const float2*)(Wacc + (size_t)ACCN * NF);   // row 1024
    const bool is_stm = (warp < BATCH);
    const float2* src = (const float2*)(is_stm ? stm + (size_t)warp * NF
                                               : nstm + (size_t)(warp - BATCH) * NF);
    __half2* dst = (__half2*)(g_F + (size_t)warp * KPAD);

    float cnt = 0.f, ps = 0.f;
    #pragma unroll
    for (int it = 0; it < 3; ++it) {
        int p = lane + it * 32;                      // pair index, KPAD/2 = 88 pairs
        if (p < 88) {
            float x = 0.f, y = 0.f;
            if (p < 81) {                            // NF/2 = 81 full pairs
                float2 v = src[p];
                x = v.x; y = v.y;
                float2 w = WaccLast[p];
                ps += x * w.x + y * w.y;
                cnt += x + y;
            }
            dst[p] = __floats2half2_rn(x, y);
        }
    }
    #pragma unroll
    for (int o = 16; o; o >>= 1) {
        cnt += __shfl_xor_sync(0xffffffffu, cnt, o);
        ps  += __shfl_xor_sync(0xffffffffu, ps,  o);
    }
    if (lane == 0) {
        if (is_stm) {
            int pc = (int)(cnt + 0.5f);
            int b  = pc / 20;
            b = (b > NB - 1) ? NB - 1 : b;
            g_bucket[warp] = b;
            atomicAdd(&g_cnt[b], 1);
            g_psqt_s[warp] = ps;
        } else {
            g_psqt_n[warp - BATCH] = ps;
        }
    }
}

// segment starts (128-aligned) + tile table (parallel fill)
__global__ void __launch_bounds__(64) prefix_kernel() {
    __shared__ int sseg[NB], sbase[NB], snt[NB];
    if (threadIdx.x == 0) {
        int s = 0, t = 0;
        #pragma unroll
        for (int b = 0; b < NB; ++b) {
            sseg[b] = s; sbase[b] = t;
            int nt = (g_cnt[b] + 127) >> 7;
            snt[b] = nt;
            g_seg[b] = s;
            t += nt; s += nt * 128;
        }
        g_ntiles = t;
    }
    __syncthreads();
    for (int b = 0; b < NB; ++b)
        for (int i = threadIdx.x; i < snt[b]; i += 64) {
            g_tilebk[sbase[b] + i] = b;
            g_tilem0[sbase[b] + i] = sseg[b] + i * 128;
        }
}

__global__ void __launch_bounds__(256) scatter_kernel() {
    int r = blockIdx.x * 256 + threadIdx.x;
    if (r >= BATCH) return;
    int b = g_bucket[r];
    int pos = g_seg[b] + atomicAdd(&g_fill[b], 1);
    g_perm[pos] = r;
}

// ---------------- GEMM1: persistent, B-resident, 512 threads, BM=128 BN=128 ----------------
#define BSTR 136    // Bs row stride (halves): 128 + 8 pad
#define ASTR 184    // As row stride (halves): 176 + 8 pad
#define G1_SMEM ((176 * BSTR + 2 * 128 * ASTR) * 2)

__global__ void __launch_bounds__(512) gemm1_kernel(const float* __restrict__ bias) {
    extern __shared__ __half sh[];
    __half* Bs = sh;                       // [176][BSTR]
    __half* As = sh + 176 * BSTR;          // [2][128][ASTR]

    const int tid  = threadIdx.x;
    const int lane = tid & 31, wid = tid >> 5;
    const int wm = wid & 3, wn = wid >> 2;          // 4 x 4 warps -> 128 x 128, warp 32x32
    const int n0 = blockIdx.y * 128;
    const int mslot = blockIdx.x;                   // 0..17

    // load B tile once: 176 rows x 128 halves = 16 chunks of 16B per row
    for (int idx = tid; idx < 176 * 16; idx += 512) {
        int k = idx >> 4, c = idx & 15;
        uint32_t d = smem_u32(Bs + k * BSTR + c * 8);
        asm volatile("cp.async.cg.shared.global [%0], [%1], 16;\n"
                     :: "r"(d), "l"(g_Wt + k * ACCN + n0 + c * 8));
    }

    auto loadA = [&](int buf, int mt) {
        const __half* base = g_F + (size_t)mt * 128 * KPAD;
        __half* dst = As + buf * (128 * ASTR);
        #pragma unroll
        for (int it = 0; it < 6; ++it) {
            int idx = tid + it * 512;                // 128 rows x 22 chunks = 2816
            if (idx < 128 * 22) {
                int r = idx / 22, c = idx - r * 22;
                asm volatile("cp.async.cg.shared.global [%0], [%1], 16;\n"
                             :: "r"(smem_u32(dst + r * ASTR + c * 8)),
                                "l"(base + (size_t)r * KPAD + c * 8));
            }
        }
    };

    loadA(0, mslot);
    asm volatile("cp.async.commit_group;\n");       // group: B + A0

    const int g = lane >> 2, t4 = lane & 3;
    int buf = 0;
    for (int mt = mslot; mt < 512; mt += 18) {
        if (mt + 18 < 512) {
            loadA(buf ^ 1, mt + 18);
            asm volatile("cp.async.commit_group;\n");
            asm volatile("cp.async.wait_group 1;\n");
        } else {
            asm volatile("cp.async.wait_group 0;\n");
        }
        __syncthreads();

        float acc[2][4][4];
        #pragma unroll
        for (int i = 0; i < 2; ++i)
            #pragma unroll
            for (int j = 0; j < 4; ++j)
                #pragma unroll
                for (int k = 0; k < 4; ++k) acc[i][j][k] = 0.f;

        const __half* Ab = As + buf * (128 * ASTR);
        #pragma unroll
        for (int kt = 0; kt < 11; ++kt) {
            uint32_t af[2][4], bf[4][2];
            #pragma unroll
            for (int mf = 0; mf < 2; ++mf) {
                const __half* p = Ab + (wm * 32 + mf * 16 + ((lane >> 3) & 1) * 8 + (lane & 7)) * ASTR
                                     + kt * 16 + (lane >> 4) * 8;
                asm volatile("ldmatrix.sync.aligned.m8n8.x4.shared.b16 {%0,%1,%2,%3}, [%4];\n"
                             : "=r"(af[mf][0]), "=r"(af[mf][1]), "=r"(af[mf][2]), "=r"(af[mf][3])
                             : "r"(smem_u32(p)));
            }
            #pragma unroll
            for (int ng = 0; ng < 2; ++ng) {
                const __half* p = Bs + (kt * 16 + ((lane >> 3) & 1) * 8 + (lane & 7)) * BSTR
                                     + wn * 32 + ng * 16 + (lane >> 4) * 8;
                uint32_t r0, r1, r2, r3;
                asm volatile("ldmatrix.sync.aligned.m8n8.x4.trans.shared.b16 {%0,%1,%2,%3}, [%4];\n"
                             : "=r"(r0), "=r"(r1), "=r"(r2), "=r"(r3) : "r"(smem_u32(p)));
                bf[ng * 2 + 0][0] = r0; bf[ng * 2 + 0][1] = r1;
                bf[ng * 2 + 1][0] = r2; bf[ng * 2 + 1][1] = r3;
            }
            #pragma unroll
            for (int mf = 0; mf < 2; ++mf)
                #pragma unroll
                for (int nf = 0; nf < 4; ++nf)
                    asm volatile(
                        "mma.sync.aligned.m16n8k16.row.col.f32.f16.f16.f32 "
                        "{%0,%1,%2,%3}, {%4,%5,%6,%7}, {%8,%9}, {%0,%1,%2,%3};\n"
                        : "+f"(acc[mf][nf][0]), "+f"(acc[mf][nf][1]),
                          "+f"(acc[mf][nf][2]), "+f"(acc[mf][nf][3])
                        : "r"(af[mf][0]), "r"(af[mf][1]), "r"(af[mf][2]), "r"(af[mf][3]),
                          "r"(bf[nf][0]), "r"(bf[nf][1]));
        }
        __syncthreads();

        // epilogue: bias + clip^2 -> g_X
        #pragma unroll
        for (int mf = 0; mf < 2; ++mf) {
            #pragma unroll
            for (int nf = 0; nf < 4; ++nf) {
                const int col = n0 + wn * 32 + nf * 8 + 2 * t4;
                #pragma unroll
                for (int h = 0; h < 2; ++h) {
                    const int row = mt * 128 + wm * 32 + mf * 16 + g + h * 8;
                    float v0 = __saturatef(acc[mf][nf][h * 2 + 0] + bias[col]);     v0 *= v0;
                    float v1 = __saturatef(acc[mf][nf][h * 2 + 1] + bias[col + 1]); v1 *= v1;
                    const size_t off = (row < BATCH)
                        ? (size_t)row * XW + col
                        : (size_t)(row - BATCH) * XW + ACCN + col;
                    *(__half2*)(g_X + off) = __floats2half2_rn(v0, v1);
                }
            }
        }
        buf ^= 1;
    }
}

// ---------------- GEMM2 + fused layers 2/3 + PSQT ----------------
#define A2STR 40
__global__ void __launch_bounds__(256) gemm2_kernel(const float* __restrict__ b1,
                                                    const float* __restrict__ W2,
                                                    const float* __restrict__ b2,
                                                    const float* __restrict__ W3,
                                                    const float* __restrict__ b3,
                                                    float* __restrict__ out) {
    __shared__ __align__(16) __half As[2][128 * A2STR];
    __shared__ __align__(16) __half Bs[2][32 * A2STR];
    __shared__ int sperm[128];
    __shared__ float sh1[128 * 33];
    __shared__ float sW2[32 * 32];
    __shared__ float sb2[32];
    __shared__ float sW3[32];
    __shared__ float sb3v;

    if (blockIdx.x >= g_ntiles) return;
    const int bk = g_tilebk[blockIdx.x];
    const int m0 = g_tilem0[blockIdx.x];

    const int tid  = threadIdx.x;
    const int lane = tid & 31, wid = tid >> 5;
    const int wm = wid & 3, wn = wid >> 2;         // warp tile 32m x 16n

    if (tid < 128) sperm[tid] = g_perm[m0 + tid];
    for (int i = tid; i < 32 * 32; i += 256) sW2[i] = W2[bk * 32 * 32 + i];
    if (tid < 32) { sb2[tid] = b2[bk * 32 + tid]; sW3[tid] = W3[bk * 32 + tid]; }
    if (tid == 0) sb3v = b3[bk];
    __syncthreads();

    const int arow = tid >> 1;
    const int ac2  = (tid & 1) * 2;
    int rp = sperm[arow]; if (rp < 0) rp = 0;
    const __half* gA = g_X + (size_t)rp * XW + ac2 * 8;
    const int brow = tid >> 2, bc = tid & 3;
    const __half* gB = g_W1t + (size_t)brow * 256 + bk * 32 + bc * 8;

    auto issue = [&](int bufi, int kt) {
        uint32_t sa = smem_u32(&As[bufi][arow * A2STR + ac2 * 8]);
        #pragma unroll
        for (int c = 0; c < 2; ++c)
            asm volatile("cp.async.cg.shared.global [%0], [%1], 16;\n"
                         :: "r"(sa + c * 16), "l"(gA + kt * 32 + c * 8));
        if (tid < 128) {
            uint32_t sb = smem_u32(&Bs[bufi][brow * A2STR + bc * 8]);
            asm volatile("cp.async.cg.shared.global [%0], [%1], 16;\n"
                         :: "r"(sb), "l"(gB + (size_t)kt * 32 * 256));
        }
        asm volatile("cp.async.commit_group;\n");
    };

    float acc[2][2][4];
    #pragma unroll
    for (int i = 0; i < 2; ++i)
        #pragma unroll
        for (int j = 0; j < 2; ++j)
            #pragma unroll
            for (int k = 0; k < 4; ++k) acc[i][j][k] = 0.f;

    issue(0, 0);
    const int KT = XW / 32;
    for (int kt = 0; kt < KT; ++kt) {
        const int bufi = kt & 1;
        if (kt + 1 < KT) {
            issue(bufi ^ 1, kt + 1);
            asm volatile("cp.async.wait_group 1;\n");
        } else {
            asm volatile("cp.async.wait_group 0;\n");
        }
        __syncthreads();

        #pragma unroll
        for (int ks = 0; ks < 2; ++ks) {
            uint32_t af[2][4], bf[2][2];
            #pragma unroll
            for (int mf = 0; mf < 2; ++mf) {
                const __half* p = &As[bufi][(wm * 32 + mf * 16 + ((lane >> 3) & 1) * 8 + (lane & 7)) * A2STR
                                            + ks * 16 + (lane >> 4) * 8];
                asm volatile("ldmatrix.sync.aligned.m8n8.x4.shared.b16 {%0,%1,%2,%3}, [%4];\n"
                             : "=r"(af[mf][0]), "=r"(af[mf][1]), "=r"(af[mf][2]), "=r"(af[mf][3])
                             : "r"(smem_u32(p)));
            }
            {
                const __half* p = &Bs[bufi][(ks * 16 + ((lane >> 3) & 1) * 8 + (lane & 7)) * A2STR
                                            + wn * 16 + (lane >> 4) * 8];
                uint32_t r0, r1, r2, r3;
                asm volatile("ldmatrix.sync.aligned.m8n8.x4.trans.shared.b16 {%0,%1,%2,%3}, [%4];\n"
                             : "=r"(r0), "=r"(r1), "=r"(r2), "=r"(r3) : "r"(smem_u32(p)));
                bf[0][0] = r0; bf[0][1] = r1;
                bf[1][0] = r2; bf[1][1] = r3;
            }
            #pragma unroll
            for (int mf = 0; mf < 2; ++mf)
                #pragma unroll
                for (int nf = 0; nf < 2; ++nf)
                    asm volatile(
                        "mma.sync.aligned.m16n8k16.row.col.f32.f16.f16.f32 "
                        "{%0,%1,%2,%3}, {%4,%5,%6,%7}, {%8,%9}, {%0,%1,%2,%3};\n"
                        : "+f"(acc[mf][nf][0]), "+f"(acc[mf][nf][1]),
                          "+f"(acc[mf][nf][2]), "+f"(acc[mf][nf][3])
                        : "r"(af[mf][0]), "r"(af[mf][1]), "r"(af[mf][2]), "r"(af[mf][3]),
                          "r"(bf[nf][0]), "r"(bf[nf][1]));
        }
        __syncthreads();
    }

    // epilogue: bias + clip -> smem h1
    const int g = lane >> 2, t4 = lane & 3;
    #pragma unroll
    for (int mf = 0; mf < 2; ++mf) {
        #pragma unroll
        for (int nf = 0; nf < 2; ++nf) {
            const int col = wn * 16 + nf * 8 + 2 * t4;
            #pragma unroll
            for (int h = 0; h < 2; ++h) {
                const int rl = wm * 32 + mf * 16 + g + h * 8;
                sh1[rl * 33 + col]     = __saturatef(acc[mf][nf][h * 2 + 0] + b1[bk * 32 + col]);
                sh1[rl * 33 + col + 1] = __saturatef(acc[mf][nf][h * 2 + 1] + b1[bk * 32 + col + 1]);
            }
        }
    }
    __syncthreads();

    // fused layers 2/3 + psqt: one thread per row
    if (tid < 128) {
        const int r = sperm[tid];
        if (r >= 0) {
            const float* hr = &sh1[tid * 33];
            float o = 0.f;
            #pragma unroll 4
            for (int i = 0; i < 32; ++i) {
                float s = sb2[i];
                const float* wr = &sW2[i * 32];
                #pragma unroll
                for (int j = 0; j < 32; ++j) s += wr[j] * hr[j];
                s = __saturatef(s);
                o += sW3[i] * s;
            }
            o += sb3v + 0.5f * (g_psqt_s[r] - g_psqt_n[r]);
            out[r] = o;
        }
    }
}

// ---------------- launch ----------------
extern "C" void kernel_launch(void* const* d_in, const int* in_sizes, int n_in,
                              void* d_out, int out_size) {
    const float* stm  = (const float*)d_in[0];
    const float* nstm = (const float*)d_in[1];
    const float* Wacc = (const float*)d_in[2];
    const float* bacc = (const float*)d_in[3];
    const float* W1   = (const float*)d_in[4];
    const float* b1   = (const float*)d_in[5];
    const float* W2   = (const float*)d_in[6];
    const float* b2   = (const float*)d_in[7];
    const float* W3   = (const float*)d_in[8];
    const float* b3   = (const float*)d_in[9];
    float* out = (float*)d_out;

    static bool attr_set = false;
    if (!attr_set) {
        cudaFuncSetAttribute(gemm1_kernel, cudaFuncAttributeMaxDynamicSharedMemorySize, G1_SMEM);
        attr_set = true;
    }

    setup_kernel<<<(XW * 256 + 255) / 256, 256>>>(Wacc, W1);
    feat_kernel<<<(2 * BATCH) / 8, 256>>>(stm, nstm, Wacc);
    prefix_kernel<<<1, 64>>>();
    scatter_kernel<<<BATCH / 256, 256>>>();

    dim3 g1(18, ACCN / 128);
    gemm1_kernel<<<g1, 512, G1_SMEM>>>(bacc);

    gemm2_kernel<<<MAXT, 256>>>(b1, W2, b2, W3, b3, out);
}